// round 4
// baseline (speedup 1.0000x reference)
#include <cuda_runtime.h>
#include <cstdint>
#include <cstddef>

#define B_ 8192
#define T_ 21
#define I_ 128
#define H1_ 256
#define H2_ 256
#define H3_ 128
#define M_ (B_*T_)   /* 172032 = 96*1792 exactly */

#define MT 96
#define SB 260            /* activation row stride (floats), ==4 mod 32 -> conflict-free frags */
#define WST 36            /* weight stage row stride (floats), ==4 mod 32 */
#define STG (3*32*WST)    /* floats per stage buffer (3 gates x 32 n x 32 k, padded) */

// -------- device scratch (allocation-free rule: __device__ globals) --------
__device__ float g_xt[(size_t)M_ * I_];   // 88 MB transposed, tf32-rounded x
__device__ float g_W1[3*H1_*I_];          // packed [i|g|o] weights, tf32-rounded
__device__ float g_W2[3*H2_*H1_];
__device__ float g_W3[3*H3_*H2_];
__device__ float g_b1[3*H1_];
__device__ float g_b2[3*H2_];
__device__ float g_b3[3*H3_];
__device__ float g_y[M_];                 // fc1 output (B,21)

// -------- helpers --------
__device__ __forceinline__ float tf32r(float f){
    uint32_t u; asm("cvt.rna.tf32.f32 %0, %1;" : "=r"(u) : "f"(f));
    return __uint_as_float(u);
}
__device__ __forceinline__ void cpa16(float* dst, const float* src){
    unsigned s = (unsigned)__cvta_generic_to_shared(dst);
    asm volatile("cp.async.ca.shared.global [%0], [%1], 16;" :: "r"(s), "l"(src));
}
__device__ __forceinline__ void cp_commit(){ asm volatile("cp.async.commit_group;"); }
template<int N> __device__ __forceinline__ void cp_wait(){ asm volatile("cp.async.wait_group %0;" :: "n"(N)); }

__device__ __forceinline__ void mma8(float* c, uint32_t a0,uint32_t a1,uint32_t a2,uint32_t a3,
                                     uint32_t b0, uint32_t b1){
    asm volatile(
      "mma.sync.aligned.m16n8k8.row.col.f32.tf32.tf32.f32 "
      "{%0,%1,%2,%3},{%4,%5,%6,%7},{%8,%9},{%0,%1,%2,%3};"
      : "+f"(c[0]),"+f"(c[1]),"+f"(c[2]),"+f"(c[3])
      : "r"(a0),"r"(a1),"r"(a2),"r"(a3),"r"(b0),"r"(b1));
}

__device__ __forceinline__ float sigmoidf_(float x){ return __fdividef(1.f, 1.f + __expf(-x)); }
__device__ __forceinline__ float tanhf2_(float x){ return 1.f - __fdividef(2.f, __expf(2.f*x) + 1.f); }

__device__ __forceinline__ int src_row(int n, int H){
    int blk = n / H, j = n - blk*H;
    return blk==0 ? j : (blk==1 ? 2*H + j : 3*H + j);   // gate order i,f,g,o: pick i,g,o
}

// -------- prep: pack + tf32-round weights, sum biases --------
__global__ void pack_kernel(const float* __restrict__ W1,const float* __restrict__ b1i,const float* __restrict__ b1h,
                            const float* __restrict__ W2,const float* __restrict__ b2i,const float* __restrict__ b2h,
                            const float* __restrict__ W3,const float* __restrict__ b3i,const float* __restrict__ b3h){
    int idx = blockIdx.x*blockDim.x + threadIdx.x;
    const int S1 = 3*H1_*I_, S2 = 3*H2_*H1_, S3 = 3*H3_*H2_;
    if (idx < S1){ int n = idx / I_,  k = idx % I_;  g_W1[idx] = tf32r(W1[(size_t)src_row(n,H1_)*I_  + k]); return; }
    idx -= S1;
    if (idx < S2){ int n = idx / H1_, k = idx % H1_; g_W2[idx] = tf32r(W2[(size_t)src_row(n,H2_)*H1_ + k]); return; }
    idx -= S2;
    if (idx < S3){ int n = idx / H2_, k = idx % H2_; g_W3[idx] = tf32r(W3[(size_t)src_row(n,H3_)*H2_ + k]); return; }
    idx -= S3;
    if (idx < 3*H1_){ int r = src_row(idx,H1_); g_b1[idx] = b1i[r] + b1h[r]; return; }
    idx -= 3*H1_;
    if (idx < 3*H2_){ int r = src_row(idx,H2_); g_b2[idx] = b2i[r] + b2h[r]; return; }
    idx -= 3*H2_;
    if (idx < 3*H3_){ int r = src_row(idx,H3_); g_b3[idx] = b3i[r] + b3h[r]; return; }
}

// -------- prep: x (B,I,T) -> xt (B*T, I), coalesced both sides, tf32-rounded --------
__global__ void transpose_kernel(const float* __restrict__ x){
    __shared__ float sx[I_*T_];
    int b = blockIdx.x, tid = threadIdx.x;   // 128 threads
    const float* xb = x + (size_t)b*I_*T_;
    #pragma unroll
    for (int j = tid; j < I_*T_; j += 128) sx[j] = xb[j];
    __syncthreads();
    #pragma unroll
    for (int t = 0; t < T_; ++t)
        g_xt[((size_t)(b*T_+t))*I_ + tid] = tf32r(sx[tid*T_ + t]);
}

// -------- fused LSTM-chain GEMM layer --------
template<int K, int H>
__device__ void layer_gemm(const float* __restrict__ Wp, const float* __restrict__ bp,
                           const float* actIn, float* actOut, float* wst, float* biasS){
    const int tid = threadIdx.x;            // 384 threads
    for (int i = tid; i < 3*H; i += 384) biasS[i] = bp[i];
    __syncthreads();
    const int warp = tid >> 5, lane = tid & 31;
    const int strip = warp >> 1, nh = warp & 1;   // 6 row strips x 2 n-halves = 12 warps
    const int g = lane >> 2, tq = lane & 3;
    const int mrow = strip*16;
    constexpr int NKC = K/32, NJC = H/32;

    for (int jc = 0; jc < NJC; ++jc){
        const int j0 = jc*32;
        float acc[3][2][4];
        #pragma unroll
        for (int a=0;a<3;++a)
            #pragma unroll
            for (int s=0;s<2;++s)
                #pragma unroll
                for (int p=0;p<4;++p) acc[a][s][p]=0.f;

        // prologue: stage kc = 0
        #pragma unroll
        for (int it=0; it<2; ++it){
            int c = tid + it*384;                          // 768 16B chunks
            int G = c >> 8, rem = c & 255, n = rem >> 3, k4 = rem & 7;
            cpa16(wst + G*(32*WST) + n*WST + k4*4,
                  Wp + (size_t)(G*H + j0 + n)*K + k4*4);
        }
        cp_commit();

        for (int kc = 0; kc < NKC; ++kc){
            if (kc+1 < NKC){
                float* dst = wst + ((kc+1)&1)*STG;
                #pragma unroll
                for (int it=0; it<2; ++it){
                    int c = tid + it*384;
                    int G = c >> 8, rem = c & 255, n = rem >> 3, k4 = rem & 7;
                    cpa16(dst + G*(32*WST) + n*WST + k4*4,
                          Wp + (size_t)(G*H + j0 + n)*K + (kc+1)*32 + k4*4);
                }
                cp_commit();
                cp_wait<1>();
            } else {
                cp_wait<0>();
            }
            __syncthreads();
            const float* ws = wst + (kc&1)*STG;
            #pragma unroll
            for (int ks=0; ks<4; ++ks){
                const int k = kc*32 + ks*8;
                const float* ar = actIn + (mrow+g)*SB + k + tq;
                uint32_t a0 = __float_as_uint(ar[0]);
                uint32_t a1 = __float_as_uint(ar[8*SB]);
                uint32_t a2 = __float_as_uint(ar[4]);
                uint32_t a3 = __float_as_uint(ar[8*SB+4]);
                #pragma unroll
                for (int G=0; G<3; ++G){
                    const float* wt = ws + G*(32*WST) + ks*8 + tq;
                    #pragma unroll
                    for (int s=0; s<2; ++s){
                        const int nl = nh*16 + s*8 + g;
                        uint32_t b0 = __float_as_uint(wt[nl*WST]);
                        uint32_t b1 = __float_as_uint(wt[nl*WST+4]);
                        mma8(acc[G][s], a0,a1,a2,a3, b0,b1);
                    }
                }
            }
            __syncthreads();
        }
        // combine: c = sig(i)*tanh(g); h = sig(o)*tanh(c)  (f-gate unused since c0=0)
        #pragma unroll
        for (int s=0; s<2; ++s){
            const int cbase = j0 + nh*16 + s*8 + 2*tq;
            #pragma unroll
            for (int p=0; p<4; ++p){
                const int q = p & 1, rr = p >> 1;
                const int c2 = cbase + q;
                float iv = acc[0][s][p] + biasS[c2];
                float gv = acc[1][s][p] + biasS[H + c2];
                float ov = acc[2][s][p] + biasS[2*H + c2];
                float cv = sigmoidf_(iv) * tanhf2_(gv);
                float h  = sigmoidf_(ov) * tanhf2_(cv);
                actOut[(mrow + g + 8*rr)*SB + c2] = tf32r(h);
            }
        }
    }
    __syncthreads();
}

__global__ void __launch_bounds__(384,1)
lstm_main(const float* __restrict__ fc1w, const float* __restrict__ fc1b){
    extern __shared__ float smem[];
    float* actA  = smem;                 // 96*260
    float* actB  = actA + MT*SB;         // 96*260
    float* wst   = actB + MT*SB;         // 2*STG
    float* biasS = wst + 2*STG;          // 768
    float* fcw   = biasS + 3*H1_;        // 128
    const int tid = threadIdx.x;
    const int m0 = blockIdx.x * MT;

    // load X tile (96 x 128) via cp.async
    #pragma unroll
    for (int it=0; it<8; ++it){
        int c = tid + it*384;            // 3072 chunks
        int r = c >> 5, k4 = c & 31;
        cpa16(actA + r*SB + k4*4, g_xt + (size_t)(m0+r)*I_ + k4*4);
    }
    if (tid < 128) fcw[tid] = fc1w[tid];
    cp_commit();
    cp_wait<0>();
    __syncthreads();

    layer_gemm<I_,  H1_>(g_W1, g_b1, actA, actB, wst, biasS);  // h1 in actB
    layer_gemm<H1_, H2_>(g_W2, g_b2, actB, actA, wst, biasS);  // h2 in actA
    layer_gemm<H2_, H3_>(g_W3, g_b3, actA, actB, wst, biasS);  // h3 in actB (96x128)

    if (tid < MT){
        const float* row = actB + tid*SB;
        float s = 0.f;
        #pragma unroll 8
        for (int i=0;i<I_;++i) s += row[i]*fcw[i];
        g_y[m0+tid] = s + fc1b[0];
    }
}

// -------- fc2: out[b,0,t] = sum_j y[b,j]*w[t,j] + bias[t] --------
__global__ void fc2_kernel(const float* __restrict__ w, const float* __restrict__ bias,
                           float* __restrict__ out){
    __shared__ float sw[T_*T_];
    __shared__ float sb[T_];
    int tid = threadIdx.x;               // 256
    for (int i = tid; i < T_*T_; i += 256) sw[i] = w[i];
    if (tid < T_) sb[tid] = bias[tid];
    __syncthreads();
    int gidx = blockIdx.x*256 + tid;     // exactly 172032 threads
    int b = gidx / T_, t = gidx - b*T_;
    const float* yb = g_y + (size_t)b*T_;
    float s = sb[t];
    #pragma unroll
    for (int j=0;j<T_;++j) s += yb[j]*sw[t*T_ + j];
    out[gidx] = s;
}

// -------- launch --------
extern "C" void kernel_launch(void* const* d_in, const int* in_sizes, int n_in,
                              void* d_out, int out_size){
    const float* x   = (const float*)d_in[0];
    const float* W1  = (const float*)d_in[1];
    const float* b1i = (const float*)d_in[2];
    const float* b1h = (const float*)d_in[3];
    const float* W2  = (const float*)d_in[4];
    const float* b2i = (const float*)d_in[5];
    const float* b2h = (const float*)d_in[6];
    const float* W3  = (const float*)d_in[7];
    const float* b3i = (const float*)d_in[8];
    const float* b3h = (const float*)d_in[9];
    const float* f1w = (const float*)d_in[10];
    const float* f1b = (const float*)d_in[11];
    const float* f2w = (const float*)d_in[12];
    const float* f2b = (const float*)d_in[13];
    float* out = (float*)d_out;

    const int SMEM_BYTES = (2*MT*SB + 2*STG + 3*H1_ + 128) * 4;  // 230912
    cudaFuncSetAttribute(lstm_main, cudaFuncAttributeMaxDynamicSharedMemorySize, SMEM_BYTES);

    pack_kernel<<<1544, 256>>>(W1,b1i,b1h,W2,b2i,b2h,W3,b3i,b3h);
    transpose_kernel<<<B_, 128>>>(x);
    lstm_main<<<M_/MT, 384, SMEM_BYTES>>>(f1w, f1b);
    fc2_kernel<<<M_/256, 256>>>(f2w, f2b, out);
}

// round 7
// speedup vs baseline: 3.7535x; 3.7535x over previous
#include <cuda_runtime.h>
#include <cuda_bf16.h>
#include <cstdint>
#include <cstddef>

#define B_ 8192
#define T_ 21
#define M_ (B_*T_)          /* 172032 = 1344*128 */
#define NTILE 1344
#define NSTAGES 64          /* 16 (L1) + 32 (L2) + 16 (L3) weight stages of 12KB */

/* smem byte offsets */
#define SO_A0    0u         /* 64KB: x (L1 in), then h2 (L3 in) */
#define SO_A1    65536u     /* 64KB: h1 (L2 in) */
#define SO_W     131072u    /* 4 x 12KB weight stage ring */
#define SO_BIAS  180224u    /* 1920 floats */
#define SO_FCW   187904u    /* 128 floats */
#define SO_RED   188416u    /* 128 floats */
#define SMEM_TOT 188928

/* ---- device scratch (allocation-free rule: __device__ globals) ---- */
__device__ __align__(128) unsigned char g_xA[(size_t)NTILE*32768];   /* per-tile swizzled bf16 x images */
__device__ __align__(128) unsigned char g_Wimg[NSTAGES*12288];       /* pre-swizzled weight stages */
__device__ float g_bias[1920];   /* [L1 i|g|o 768, L2 768, L3 384] */
__device__ float g_y[M_];

/* ---- helpers ---- */
__device__ __forceinline__ uint32_t s2u(const void* p){ return (uint32_t)__cvta_generic_to_shared(p); }
__device__ __forceinline__ void cpa16(void* dst, const void* src){
    asm volatile("cp.async.ca.shared.global [%0], [%1], 16;" :: "r"(s2u(dst)), "l"(src));
}
__device__ __forceinline__ void cp_commit(){ asm volatile("cp.async.commit_group;"); }
template<int N> __device__ __forceinline__ void cp_wait(){ asm volatile("cp.async.wait_group %0;" :: "n"(N)); }

__device__ __forceinline__ void ldsm4(uint32_t* r, const void* p){
    asm volatile("ldmatrix.sync.aligned.m8n8.x4.shared.b16 {%0,%1,%2,%3}, [%4];"
        : "=r"(r[0]),"=r"(r[1]),"=r"(r[2]),"=r"(r[3]) : "r"(s2u(p)));
}
__device__ __forceinline__ void mma16816(float* c, const uint32_t* a, uint32_t b0, uint32_t b1){
    asm volatile("mma.sync.aligned.m16n8k16.row.col.f32.bf16.bf16.f32 "
        "{%0,%1,%2,%3},{%4,%5,%6,%7},{%8,%9},{%0,%1,%2,%3};"
        : "+f"(c[0]),"+f"(c[1]),"+f"(c[2]),"+f"(c[3])
        : "r"(a[0]),"r"(a[1]),"r"(a[2]),"r"(a[3]),"r"(b0),"r"(b1));
}
__device__ __forceinline__ uint32_t pk2(float lo, float hi){
    uint32_t r; asm("cvt.rn.bf16x2.f32 %0, %1, %2;" : "=r"(r) : "f"(hi), "f"(lo)); return r;
}
__device__ __forceinline__ float sigf(float x){ return __fdividef(1.f, 1.f + __expf(-x)); }
__device__ __forceinline__ float tanh2f(float x){ return 1.f - __fdividef(2.f, __expf(2.f*x) + 1.f); }
__device__ __forceinline__ float hval(float iv, float gv, float ov){
    float cv = sigf(iv) * tanh2f(gv);
    return sigf(ov) * tanh2f(cv);
}

/* ---- prep: weights -> pre-swizzled 12KB stages in consumption order ---- */
/* stage = 96 rows (3 gates x 32 n) x 64 k bf16; row 128B; chunk swizzle c^(n&7) */
__global__ void pack_kernel(const float* __restrict__ W1,const float* __restrict__ b1i,const float* __restrict__ b1h,
                            const float* __restrict__ W2,const float* __restrict__ b2i,const float* __restrict__ b2h,
                            const float* __restrict__ W3,const float* __restrict__ b3i,const float* __restrict__ b3h){
    int idx = blockIdx.x*256 + threadIdx.x;
    if (idx < NSTAGES*6144){
        int ss = idx / 6144, e = idx % 6144;
        int nrow = e >> 6, kk = e & 63;
        int l, jc, kc;
        if (ss < 16){ l = 0; jc = ss >> 1; kc = ss & 1; }
        else if (ss < 48){ int s = ss-16; l = 1; jc = s >> 2; kc = s & 3; }
        else { int s = ss-48; l = 2; jc = s >> 2; kc = s & 3; }
        int g = nrow >> 5, n = nrow & 31;
        int H = (l<2) ? 256 : 128;
        int K = (l==0) ? 128 : 256;
        int j = jc*32 + n;
        int row = (g==0) ? j : (g==1) ? 2*H+j : 3*H+j;   /* gates i,g,o from i,f,g,o */
        const float* W = (l==0) ? W1 : (l==1) ? W2 : W3;
        float v = W[(size_t)row*K + kc*64 + kk];
        uint32_t off = (uint32_t)nrow*128u + ((((uint32_t)(kk>>3)) ^ (nrow&7))<<4) + ((2u*kk)&15);
        *reinterpret_cast<__nv_bfloat16*>(g_Wimg + (size_t)ss*12288 + off) = __float2bfloat16_rn(v);
        return;
    }
    idx -= NSTAGES*6144;
    if (idx < 1920){
        int l = (idx<768)?0:(idx<1536)?1:2;
        int base = (l==0)?0:(l==1)?768:1536;
        int H = (l<2)?256:128;
        int q = idx - base, g = q / H, j = q % H;
        int row = (g==0)? j : (g==1)? 2*H+j : 3*H+j;
        const float* bi = (l==0)?b1i:(l==1)?b2i:b3i;
        const float* bh = (l==0)?b1h:(l==1)?b2h:b3h;
        g_bias[idx] = bi[row] + bh[row];
    }
}

/* ---- prep: x (B,128,21) -> per-tile swizzled bf16 A images (row 256B) ---- */
__global__ void transpose_kernel(const float* __restrict__ x){
    __shared__ float sx[2688];
    int b = blockIdx.x, tid = threadIdx.x;   /* 256 threads */
    const float* xb = x + (size_t)b*2688;
    for (int i = tid; i < 2688; i += 256) sx[i] = xb[i];
    __syncthreads();
    for (int i = tid; i < 1344; i += 256){
        int t = i >> 6, kp = (i & 63) * 2;
        int m = b*21 + t, tt = m >> 7, r = m & 127;
        uint32_t v = pk2(sx[kp*21 + t], sx[(kp+1)*21 + t]);
        uint32_t off = (uint32_t)r*256u + ((((uint32_t)(kp>>3)) ^ (r&7))<<4) + ((2u*kp)&15);
        *reinterpret_cast<uint32_t*>(g_xA + (size_t)tt*32768 + off) = v;
    }
}

/* ---- weight stage fill: pure linear copy (image pre-swizzled) ---- */
__device__ __forceinline__ void fill_stage(char* smem, int s, int tid){
    char* dst = smem + SO_W + (uint32_t)(s&3)*12288u;
    const unsigned char* src = g_Wimg + (size_t)s*12288;
    #pragma unroll
    for (int it = 0; it < 3; ++it){
        int ch = tid + it*256;
        cpa16(dst + ch*16, src + ch*16);
    }
}

/* ---- one fused layer: [128 x K] @ [K x 3H] + activation combine ---- */
template<int K, int H, int LAST>
__device__ __forceinline__ void run_layer(char* smem, const char* Ain, char* Aout,
                                          int& ss, const float* biasL, const float* fcw,
                                          float* yp, int tid){
    const int wid = tid >> 5, lane = tid & 31;
    const int mw = wid >> 1, nw = wid & 1;
    const uint32_t arow = 32*mw + (lane & 15);
    const uint32_t ax = arow & 7;
    const uint32_t nrow = nw*16 + 8*(lane>>4) + (lane & 7);
    const uint32_t bx = nrow & 7;
    constexpr int NJ = H/32, NK = K/64;

    for (int jc = 0; jc < NJ; ++jc){
        float acc[3][2][2][4];
        #pragma unroll
        for (int g=0; g<3; ++g)
            #pragma unroll
            for (int mf=0; mf<2; ++mf)
                #pragma unroll
                for (int nf=0; nf<2; ++nf)
                    #pragma unroll
                    for (int p=0; p<4; ++p) acc[g][mf][nf][p] = 0.f;

        for (int kc = 0; kc < NK; ++kc){
            cp_wait<2>();
            __syncthreads();
            const char* ws = smem + SO_W + (uint32_t)(ss&3)*12288u;
            #pragma unroll
            for (int ks = 0; ks < 4; ++ks){
                const uint32_t cA = (uint32_t)(kc*8 + 2*ks) + (lane>>4);
                const uint32_t aoff = arow*(2u*K) + (((cA ^ ax))<<4);
                uint32_t a0[4], a1[4];
                ldsm4(a0, Ain + aoff);
                ldsm4(a1, Ain + aoff + 32u*K);
                const uint32_t cb = (uint32_t)(2*ks) + ((lane>>3)&1);
                const uint32_t boff = nrow*128u + (((cb ^ bx))<<4);
                uint32_t b0[4], b1[4], b2[4];
                ldsm4(b0, ws + boff);
                ldsm4(b1, ws + boff + 4096);
                ldsm4(b2, ws + boff + 8192);
                mma16816(acc[0][0][0], a0, b0[0], b0[1]);
                mma16816(acc[0][0][1], a0, b0[2], b0[3]);
                mma16816(acc[0][1][0], a1, b0[0], b0[1]);
                mma16816(acc[0][1][1], a1, b0[2], b0[3]);
                mma16816(acc[1][0][0], a0, b1[0], b1[1]);
                mma16816(acc[1][0][1], a0, b1[2], b1[3]);
                mma16816(acc[1][1][0], a1, b1[0], b1[1]);
                mma16816(acc[1][1][1], a1, b1[2], b1[3]);
                mma16816(acc[2][0][0], a0, b2[0], b2[1]);
                mma16816(acc[2][0][1], a0, b2[2], b2[3]);
                mma16816(acc[2][1][0], a1, b2[0], b2[1]);
                mma16816(acc[2][1][1], a1, b2[2], b2[3]);
            }
            __syncthreads();
            if (ss + 3 < NSTAGES) fill_stage(smem, ss + 3, tid);
            cp_commit();                  /* unconditional: keeps wait_group accounting exact */
            ++ss;
        }

        /* epilogue: combine gates -> h; store bf16 pairs (or fc1 partials) */
        #pragma unroll
        for (int nf = 0; nf < 2; ++nf){
            const int j0 = jc*32 + nw*16 + nf*8 + 2*(lane & 3);
            const float bi0 = biasL[j0],       bi1 = biasL[j0+1];
            const float bg0 = biasL[H+j0],     bg1 = biasL[H+j0+1];
            const float bo0 = biasL[2*H+j0],   bo1 = biasL[2*H+j0+1];
            #pragma unroll
            for (int mf = 0; mf < 2; ++mf){
                #pragma unroll
                for (int hf = 0; hf < 2; ++hf){
                    const float h0 = hval(acc[0][mf][nf][2*hf]   + bi0,
                                          acc[1][mf][nf][2*hf]   + bg0,
                                          acc[2][mf][nf][2*hf]   + bo0);
                    const float h1 = hval(acc[0][mf][nf][2*hf+1] + bi1,
                                          acc[1][mf][nf][2*hf+1] + bg1,
                                          acc[2][mf][nf][2*hf+1] + bo1);
                    if (LAST == 0){
                        const uint32_t row = 32*mw + 16*mf + 8*hf + (lane>>2);
                        const uint32_t b = 2u*(uint32_t)j0;
                        const uint32_t off = row*(2u*H) + ((((b>>4) ^ (row&7)))<<4) + (b&15);
                        *reinterpret_cast<uint32_t*>(Aout + off) = pk2(h0, h1);
                    } else {
                        yp[mf*2+hf] = fmaf(h0, fcw[j0], fmaf(h1, fcw[j0+1], yp[mf*2+hf]));
                    }
                }
            }
        }
    }
}

/* ---- fused main kernel: 3 LSTM layers + fc1 ---- */
__global__ void __launch_bounds__(256,1)
lstm_main(const float* __restrict__ fc1w, const float* __restrict__ fc1b){
    extern __shared__ char smem[];
    char* A0 = smem + SO_A0;
    char* A1 = smem + SO_A1;
    float* biasS = (float*)(smem + SO_BIAS);
    float* fcw   = (float*)(smem + SO_FCW);
    float* red   = (float*)(smem + SO_RED);
    const int tid = threadIdx.x, lane = tid & 31, wid = tid >> 5;
    const int mw = wid >> 1, nw = wid & 1;
    const float fc1b0 = __ldg(fc1b);

    /* x tile -> A0 (group 0) */
    #pragma unroll
    for (int it = 0; it < 8; ++it){
        int ch = tid + it*256;
        cpa16(A0 + ch*16, g_xA + (size_t)blockIdx.x*32768 + ch*16);
    }
    cp_commit();
    /* stage prologue: 3 deep */
    fill_stage(smem, 0, tid); cp_commit();
    fill_stage(smem, 1, tid); cp_commit();
    fill_stage(smem, 2, tid); cp_commit();

    for (int i = tid; i < 1920; i += 256) biasS[i] = g_bias[i];
    if (tid < 128) fcw[tid] = fc1w[tid];

    int ss = 0;
    float yp[4] = {0.f, 0.f, 0.f, 0.f};
    run_layer<128,256,0>(smem, A0, A1, ss, biasS,        fcw, yp, tid);
    run_layer<256,256,0>(smem, A1, A0, ss, biasS + 768,  fcw, yp, tid);
    run_layer<256,128,1>(smem, A0, A1, ss, biasS + 1536, fcw, yp, tid);

    /* fc1 reduce: sum across quad lanes, then across nw halves */
    #pragma unroll
    for (int k = 0; k < 4; ++k){
        yp[k] += __shfl_xor_sync(0xffffffffu, yp[k], 1);
        yp[k] += __shfl_xor_sync(0xffffffffu, yp[k], 2);
    }
    __syncthreads();
    if (nw == 0 && (lane & 3) == 0){
        #pragma unroll
        for (int k = 0; k < 4; ++k){
            int row = 32*mw + 16*(k>>1) + 8*(k&1) + (lane>>2);
            red[row] = yp[k];
        }
    }
    __syncthreads();
    if (nw == 1 && (lane & 3) == 0){
        #pragma unroll
        for (int k = 0; k < 4; ++k){
            int row = 32*mw + 16*(k>>1) + 8*(k&1) + (lane>>2);
            g_y[(size_t)blockIdx.x*128 + row] = red[row] + yp[k] + fc1b0;
        }
    }
}

/* ---- fc2: out[b,0,t] = sum_j y[b,j]*w[t,j] + bias[t] ---- */
__global__ void fc2_kernel(const float* __restrict__ w, const float* __restrict__ bias,
                           float* __restrict__ out){
    __shared__ float sw[T_*T_];
    __shared__ float sbv[T_];
    int tid = threadIdx.x;
    for (int i = tid; i < T_*T_; i += 256) sw[i] = w[i];
    if (tid < T_) sbv[tid] = bias[tid];
    __syncthreads();
    int gidx = blockIdx.x*256 + tid;
    int b = gidx / T_, t = gidx - b*T_;
    const float* yb = g_y + (size_t)b*T_;
    float s = sbv[t];
    #pragma unroll
    for (int j = 0; j < T_; ++j) s += yb[j]*sw[t*T_ + j];
    out[gidx] = s;
}

/* ---- launch ---- */
extern "C" void kernel_launch(void* const* d_in, const int* in_sizes, int n_in,
                              void* d_out, int out_size){
    const float* x   = (const float*)d_in[0];
    const float* W1  = (const float*)d_in[1];
    const float* b1i = (const float*)d_in[2];
    const float* b1h = (const float*)d_in[3];
    const float* W2  = (const float*)d_in[4];
    const float* b2i = (const float*)d_in[5];
    const float* b2h = (const float*)d_in[6];
    const float* W3  = (const float*)d_in[7];
    const float* b3i = (const float*)d_in[8];
    const float* b3h = (const float*)d_in[9];
    const float* f1w = (const float*)d_in[10];
    const float* f1b = (const float*)d_in[11];
    const float* f2w = (const float*)d_in[12];
    const float* f2b = (const float*)d_in[13];
    float* out = (float*)d_out;

    cudaFuncSetAttribute(lstm_main, cudaFuncAttributeMaxDynamicSharedMemorySize, SMEM_TOT);

    pack_kernel<<<1544, 256>>>(W1,b1i,b1h,W2,b2i,b2h,W3,b3i,b3h);
    transpose_kernel<<<B_, 256>>>(x);
    lstm_main<<<NTILE, 256, SMEM_TOT>>>(f1w, f1b);
    fc2_kernel<<<M_/256, 256>>>(f2w, f2b, out);
}

// round 8
// speedup vs baseline: 4.2310x; 1.1272x over previous
#include <cuda_runtime.h>
#include <cuda_bf16.h>
#include <cstdint>
#include <cstddef>

#define B_ 8192
#define T_ 21
#define M_ (B_*T_)          /* 172032 = 1344*128 */
#define NTILE 1344
#define NSTAGES 64          /* 16 (L1) + 32 (L2) + 16 (L3) weight stages of 12KB */

/* smem byte offsets */
#define SO_A0    0u         /* 64KB: x (L1 in), then h2 (L3 in) */
#define SO_A1    65536u     /* 64KB: h1 (L2 in) */
#define SO_W     131072u    /* 4 x 12KB weight stage ring */
#define SO_BIAS  180224u    /* 1920 floats */
#define SO_FCW   187904u    /* 128 floats */
#define SO_RED   188416u    /* 128 floats */
#define SMEM_TOT 188928

/* ---- device scratch (allocation-free rule: __device__ globals) ---- */
__device__ __align__(128) unsigned char g_xA[(size_t)NTILE*32768];   /* per-tile swizzled bf16 x images */
__device__ __align__(128) unsigned char g_Wimg[NSTAGES*12288];       /* pre-swizzled weight stages */
__device__ float g_bias[1920];   /* [L1 i|g|o 768, L2 768, L3 384] */
__device__ float g_y[M_];

/* ---- helpers ---- */
__device__ __forceinline__ uint32_t s2u(const void* p){ return (uint32_t)__cvta_generic_to_shared(p); }
__device__ __forceinline__ void cpa16(void* dst, const void* src){
    asm volatile("cp.async.ca.shared.global [%0], [%1], 16;" :: "r"(s2u(dst)), "l"(src));
}
__device__ __forceinline__ void cp_commit(){ asm volatile("cp.async.commit_group;"); }
template<int N> __device__ __forceinline__ void cp_wait(){ asm volatile("cp.async.wait_group %0;" :: "n"(N)); }

__device__ __forceinline__ void ldsm4(uint32_t* r, const void* p){
    asm volatile("ldmatrix.sync.aligned.m8n8.x4.shared.b16 {%0,%1,%2,%3}, [%4];"
        : "=r"(r[0]),"=r"(r[1]),"=r"(r[2]),"=r"(r[3]) : "r"(s2u(p)));
}
__device__ __forceinline__ void mma16816(float* c, const uint32_t* a, uint32_t b0, uint32_t b1){
    asm volatile("mma.sync.aligned.m16n8k16.row.col.f32.bf16.bf16.f32 "
        "{%0,%1,%2,%3},{%4,%5,%6,%7},{%8,%9},{%0,%1,%2,%3};"
        : "+f"(c[0]),"+f"(c[1]),"+f"(c[2]),"+f"(c[3])
        : "r"(a[0]),"r"(a[1]),"r"(a[2]),"r"(a[3]),"r"(b0),"r"(b1));
}
__device__ __forceinline__ uint32_t pk2(float lo, float hi){
    uint32_t r; asm("cvt.rn.bf16x2.f32 %0, %1, %2;" : "=r"(r) : "f"(hi), "f"(lo)); return r;
}
/* fast activations: 4 MUFU per hval (was 8) */
__device__ __forceinline__ float tanhap(float x){
    float y; asm("tanh.approx.f32 %0, %1;" : "=f"(y) : "f"(x)); return y;
}
__device__ __forceinline__ float sigap(float x){ return fmaf(tanhap(0.5f*x), 0.5f, 0.5f); }
__device__ __forceinline__ float hval(float iv, float gv, float ov){
    float cv = sigap(iv) * tanhap(gv);
    return sigap(ov) * tanhap(cv);
}

/* ---- prep: weights -> pre-swizzled 12KB stages in consumption order ---- */
/* stage = 96 rows (3 gates x 32 n) x 64 k bf16; row 128B; chunk swizzle c^(n&7) */
__global__ void pack_kernel(const float* __restrict__ W1,const float* __restrict__ b1i,const float* __restrict__ b1h,
                            const float* __restrict__ W2,const float* __restrict__ b2i,const float* __restrict__ b2h,
                            const float* __restrict__ W3,const float* __restrict__ b3i,const float* __restrict__ b3h){
    int idx = blockIdx.x*256 + threadIdx.x;
    if (idx < NSTAGES*6144){
        int ss = idx / 6144, e = idx % 6144;
        int nrow = e >> 6, kk = e & 63;
        int l, jc, kc;
        if (ss < 16){ l = 0; jc = ss >> 1; kc = ss & 1; }
        else if (ss < 48){ int s = ss-16; l = 1; jc = s >> 2; kc = s & 3; }
        else { int s = ss-48; l = 2; jc = s >> 2; kc = s & 3; }
        int g = nrow >> 5, n = nrow & 31;
        int H = (l<2) ? 256 : 128;
        int K = (l==0) ? 128 : 256;
        int j = jc*32 + n;
        int row = (g==0) ? j : (g==1) ? 2*H+j : 3*H+j;   /* gates i,g,o from i,f,g,o */
        const float* W = (l==0) ? W1 : (l==1) ? W2 : W3;
        float v = W[(size_t)row*K + kc*64 + kk];
        uint32_t off = (uint32_t)nrow*128u + ((((uint32_t)(kk>>3)) ^ (nrow&7))<<4) + ((2u*kk)&15);
        *reinterpret_cast<__nv_bfloat16*>(g_Wimg + (size_t)ss*12288 + off) = __float2bfloat16_rn(v);
        return;
    }
    idx -= NSTAGES*6144;
    if (idx < 1920){
        int l = (idx<768)?0:(idx<1536)?1:2;
        int base = (l==0)?0:(l==1)?768:1536;
        int H = (l<2)?256:128;
        int q = idx - base, g = q / H, j = q % H;
        int row = (g==0)? j : (g==1)? 2*H+j : 3*H+j;
        const float* bi = (l==0)?b1i:(l==1)?b2i:b3i;
        const float* bh = (l==0)?b1h:(l==1)?b2h:b3h;
        g_bias[idx] = bi[row] + bh[row];
    }
}

/* ---- prep: x (B,128,21) -> per-tile swizzled bf16 A images (row 256B) ---- */
__global__ void transpose_kernel(const float* __restrict__ x){
    __shared__ float sx[2688];
    int b = blockIdx.x, tid = threadIdx.x;   /* 256 threads */
    const float* xb = x + (size_t)b*2688;
    for (int i = tid; i < 2688; i += 256) sx[i] = xb[i];
    __syncthreads();
    for (int i = tid; i < 1344; i += 256){
        int t = i >> 6, kp = (i & 63) * 2;
        int m = b*21 + t, tt = m >> 7, r = m & 127;
        uint32_t v = pk2(sx[kp*21 + t], sx[(kp+1)*21 + t]);
        uint32_t off = (uint32_t)r*256u + ((((uint32_t)(kp>>3)) ^ (r&7))<<4) + ((2u*kp)&15);
        *reinterpret_cast<uint32_t*>(g_xA + (size_t)tt*32768 + off) = v;
    }
}

/* ---- weight stage fill: pure linear copy (image pre-swizzled) ---- */
__device__ __forceinline__ void fill_stage(char* smem, int s, int tid){
    char* dst = smem + SO_W + (uint32_t)(s&3)*12288u;
    const unsigned char* src = g_Wimg + (size_t)s*12288;
    #pragma unroll
    for (int it = 0; it < 3; ++it){
        int ch = tid + it*256;
        cpa16(dst + ch*16, src + ch*16);
    }
}

/* ---- one fused layer: [128 x K] @ [K x 3H] + activation combine ---- */
template<int K, int H, int LAST>
__device__ __forceinline__ void run_layer(char* smem, const char* Ain, char* Aout,
                                          int& ss, const float* biasL, const float* fcw,
                                          float* yp, int tid){
    const int wid = tid >> 5, lane = tid & 31;
    const int mw = wid >> 1, nw = wid & 1;
    const uint32_t arow = 32*mw + (lane & 15);
    const uint32_t ax = arow & 7;
    const uint32_t nrow = nw*16 + 8*(lane>>4) + (lane & 7);
    const uint32_t bx = nrow & 7;
    constexpr int NJ = H/32, NK = K/64;

    for (int jc = 0; jc < NJ; ++jc){
        float acc[3][2][2][4];
        #pragma unroll
        for (int g=0; g<3; ++g)
            #pragma unroll
            for (int mf=0; mf<2; ++mf)
                #pragma unroll
                for (int nf=0; nf<2; ++nf)
                    #pragma unroll
                    for (int p=0; p<4; ++p) acc[g][mf][nf][p] = 0.f;

        for (int kc = 0; kc < NK; ++kc){
            cp_wait<2>();
            __syncthreads();           /* all threads' pieces of stage ss visible */
            const char* ws = smem + SO_W + (uint32_t)(ss&3)*12288u;
            #pragma unroll
            for (int ks = 0; ks < 4; ++ks){
                const uint32_t cA = (uint32_t)(kc*8 + 2*ks) + (lane>>4);
                const uint32_t aoff = arow*(2u*K) + (((cA ^ ax))<<4);
                uint32_t a0[4], a1[4];
                ldsm4(a0, Ain + aoff);
                ldsm4(a1, Ain + aoff + 32u*K);
                const uint32_t cb = (uint32_t)(2*ks) + ((lane>>3)&1);
                const uint32_t boff = nrow*128u + (((cb ^ bx))<<4);
                uint32_t b0[4], b1[4], b2[4];
                ldsm4(b0, ws + boff);
                ldsm4(b1, ws + boff + 4096);
                ldsm4(b2, ws + boff + 8192);
                mma16816(acc[0][0][0], a0, b0[0], b0[1]);
                mma16816(acc[0][0][1], a0, b0[2], b0[3]);
                mma16816(acc[0][1][0], a1, b0[0], b0[1]);
                mma16816(acc[0][1][1], a1, b0[2], b0[3]);
                mma16816(acc[1][0][0], a0, b1[0], b1[1]);
                mma16816(acc[1][0][1], a0, b1[2], b1[3]);
                mma16816(acc[1][1][0], a1, b1[0], b1[1]);
                mma16816(acc[1][1][1], a1, b1[2], b1[3]);
                mma16816(acc[2][0][0], a0, b2[0], b2[1]);
                mma16816(acc[2][0][1], a0, b2[2], b2[3]);
                mma16816(acc[2][1][0], a1, b2[0], b2[1]);
                mma16816(acc[2][1][1], a1, b2[2], b2[3]);
            }
            /* no second barrier: fill targets stage (ss+3)&3, never the one
               being read; LDSM results were consumed before any thread can
               reach the next kc's barrier */
            if (ss + 3 < NSTAGES) fill_stage(smem, ss + 3, tid);
            cp_commit();                  /* unconditional: keeps wait_group accounting exact */
            ++ss;
        }

        /* epilogue: combine gates -> h; store bf16 pairs (or fc1 partials) */
        #pragma unroll
        for (int nf = 0; nf < 2; ++nf){
            const int j0 = jc*32 + nw*16 + nf*8 + 2*(lane & 3);
            const float bi0 = biasL[j0],       bi1 = biasL[j0+1];
            const float bg0 = biasL[H+j0],     bg1 = biasL[H+j0+1];
            const float bo0 = biasL[2*H+j0],   bo1 = biasL[2*H+j0+1];
            #pragma unroll
            for (int mf = 0; mf < 2; ++mf){
                #pragma unroll
                for (int hf = 0; hf < 2; ++hf){
                    const float h0 = hval(acc[0][mf][nf][2*hf]   + bi0,
                                          acc[1][mf][nf][2*hf]   + bg0,
                                          acc[2][mf][nf][2*hf]   + bo0);
                    const float h1 = hval(acc[0][mf][nf][2*hf+1] + bi1,
                                          acc[1][mf][nf][2*hf+1] + bg1,
                                          acc[2][mf][nf][2*hf+1] + bo1);
                    if (LAST == 0){
                        const uint32_t row = 32*mw + 16*mf + 8*hf + (lane>>2);
                        const uint32_t b = 2u*(uint32_t)j0;
                        const uint32_t off = row*(2u*H) + ((((b>>4) ^ (row&7)))<<4) + (b&15);
                        *reinterpret_cast<uint32_t*>(Aout + off) = pk2(h0, h1);
                    } else {
                        yp[mf*2+hf] = fmaf(h0, fcw[j0], fmaf(h1, fcw[j0+1], yp[mf*2+hf]));
                    }
                }
            }
        }
    }
}

/* ---- fused main kernel: 3 LSTM layers + fc1 ---- */
__global__ void __launch_bounds__(256,1)
lstm_main(const float* __restrict__ fc1w, const float* __restrict__ fc1b){
    extern __shared__ char smem[];
    char* A0 = smem + SO_A0;
    char* A1 = smem + SO_A1;
    float* biasS = (float*)(smem + SO_BIAS);
    float* fcw   = (float*)(smem + SO_FCW);
    float* red   = (float*)(smem + SO_RED);
    const int tid = threadIdx.x, lane = tid & 31, wid = tid >> 5;
    const int mw = wid >> 1, nw = wid & 1;
    const float fc1b0 = __ldg(fc1b);

    /* x tile -> A0 (group 0) */
    #pragma unroll
    for (int it = 0; it < 8; ++it){
        int ch = tid + it*256;
        cpa16(A0 + ch*16, g_xA + (size_t)blockIdx.x*32768 + ch*16);
    }
    cp_commit();
    /* stage prologue: 3 deep */
    fill_stage(smem, 0, tid); cp_commit();
    fill_stage(smem, 1, tid); cp_commit();
    fill_stage(smem, 2, tid); cp_commit();

    for (int i = tid; i < 1920; i += 256) biasS[i] = g_bias[i];
    if (tid < 128) fcw[tid] = fc1w[tid];

    int ss = 0;
    float yp[4] = {0.f, 0.f, 0.f, 0.f};
    run_layer<128,256,0>(smem, A0, A1, ss, biasS,        fcw, yp, tid);
    run_layer<256,256,0>(smem, A1, A0, ss, biasS + 768,  fcw, yp, tid);
    run_layer<256,128,1>(smem, A0, A1, ss, biasS + 1536, fcw, yp, tid);

    /* fc1 reduce: sum across quad lanes, then across nw halves */
    #pragma unroll
    for (int k = 0; k < 4; ++k){
        yp[k] += __shfl_xor_sync(0xffffffffu, yp[k], 1);
        yp[k] += __shfl_xor_sync(0xffffffffu, yp[k], 2);
    }
    __syncthreads();
    if (nw == 0 && (lane & 3) == 0){
        #pragma unroll
        for (int k = 0; k < 4; ++k){
            int row = 32*mw + 16*(k>>1) + 8*(k&1) + (lane>>2);
            red[row] = yp[k];
        }
    }
    __syncthreads();
    if (nw == 1 && (lane & 3) == 0){
        #pragma unroll
        for (int k = 0; k < 4; ++k){
            int row = 32*mw + 16*(k>>1) + 8*(k&1) + (lane>>2);
            g_y[(size_t)blockIdx.x*128 + row] = red[row] + yp[k] + fc1b0;
        }
    }
}

/* ---- fc2: out[b,0,t] = sum_j y[b,j]*w[t,j] + bias[t] ---- */
__global__ void fc2_kernel(const float* __restrict__ w, const float* __restrict__ bias,
                           float* __restrict__ out){
    __shared__ float sw[T_*T_];
    __shared__ float sbv[T_];
    int tid = threadIdx.x;
    for (int i = tid; i < T_*T_; i += 256) sw[i] = w[i];
    if (tid < T_) sbv[tid] = bias[tid];
    __syncthreads();
    int gidx = blockIdx.x*256 + tid;
    int b = gidx / T_, t = gidx - b*T_;
    const float* yb = g_y + (size_t)b*T_;
    float s = sbv[t];
    #pragma unroll
    for (int j = 0; j < T_; ++j) s += yb[j]*sw[t*T_ + j];
    out[gidx] = s;
}

/* ---- launch ---- */
extern "C" void kernel_launch(void* const* d_in, const int* in_sizes, int n_in,
                              void* d_out, int out_size){
    const float* x   = (const float*)d_in[0];
    const float* W1  = (const float*)d_in[1];
    const float* b1i = (const float*)d_in[2];
    const float* b1h = (const float*)d_in[3];
    const float* W2  = (const float*)d_in[4];
    const float* b2i = (const float*)d_in[5];
    const float* b2h = (const float*)d_in[6];
    const float* W3  = (const float*)d_in[7];
    const float* b3i = (const float*)d_in[8];
    const float* b3h = (const float*)d_in[9];
    const float* f1w = (const float*)d_in[10];
    const float* f1b = (const float*)d_in[11];
    const float* f2w = (const float*)d_in[12];
    const float* f2b = (const float*)d_in[13];
    float* out = (float*)d_out;

    cudaFuncSetAttribute(lstm_main, cudaFuncAttributeMaxDynamicSharedMemorySize, SMEM_TOT);

    pack_kernel<<<1544, 256>>>(W1,b1i,b1h,W2,b2i,b2h,W3,b3i,b3h);
    transpose_kernel<<<B_, 256>>>(x);
    lstm_main<<<NTILE, 256, SMEM_TOT>>>(f1w, f1b);
    fc2_kernel<<<M_/256, 256>>>(f2w, f2b, out);
}

// round 9
// speedup vs baseline: 4.7451x; 1.1215x over previous
#include <cuda_runtime.h>
#include <cuda_bf16.h>
#include <cstdint>
#include <cstddef>

#define B_ 8192
#define T_ 21
#define M_ (B_*T_)          /* 172032 = 1344*128 */
#define NTILE 1344
#define NSTAGES 64          /* 16 (L1) + 32 (L2) + 16 (L3) weight stages of 12KB */

/* smem byte offsets */
#define SO_A0    0u         /* 64KB: x (L1 in), then h2 (L3 in) */
#define SO_A1    65536u     /* 64KB: h1 (L2 in) */
#define SO_W     131072u    /* 4 x 12KB weight stage ring */
#define SO_BIAS  180224u    /* 1920 floats */
#define SO_FCW   187904u    /* 128 floats */
#define SO_RED   188416u    /* 128 floats */
#define SMEM_TOT 188928

/* ---- device scratch (allocation-free rule: __device__ globals) ---- */
__device__ __align__(128) unsigned char g_xA[(size_t)NTILE*32768];   /* per-tile swizzled bf16 x images */
__device__ __align__(128) unsigned char g_Wimg[NSTAGES*12288];       /* pre-swizzled weight stages */
__device__ float g_bias[1920];   /* [L1 i|g|o 768, L2 768, L3 384] */
__device__ float g_y[M_];

/* ---- helpers ---- */
__device__ __forceinline__ uint32_t s2u(const void* p){ return (uint32_t)__cvta_generic_to_shared(p); }
__device__ __forceinline__ void cpa16(void* dst, const void* src){
    asm volatile("cp.async.ca.shared.global [%0], [%1], 16;" :: "r"(s2u(dst)), "l"(src));
}
__device__ __forceinline__ void cp_commit(){ asm volatile("cp.async.commit_group;"); }
template<int N> __device__ __forceinline__ void cp_wait(){ asm volatile("cp.async.wait_group %0;" :: "n"(N)); }

__device__ __forceinline__ void ldsm4(uint32_t* r, const void* p){
    asm volatile("ldmatrix.sync.aligned.m8n8.x4.shared.b16 {%0,%1,%2,%3}, [%4];"
        : "=r"(r[0]),"=r"(r[1]),"=r"(r[2]),"=r"(r[3]) : "r"(s2u(p)));
}
__device__ __forceinline__ void mma16816(float* c, const uint32_t* a, uint32_t b0, uint32_t b1){
    asm volatile("mma.sync.aligned.m16n8k16.row.col.f32.bf16.bf16.f32 "
        "{%0,%1,%2,%3},{%4,%5,%6,%7},{%8,%9},{%0,%1,%2,%3};"
        : "+f"(c[0]),"+f"(c[1]),"+f"(c[2]),"+f"(c[3])
        : "r"(a[0]),"r"(a[1]),"r"(a[2]),"r"(a[3]),"r"(b0),"r"(b1));
}
__device__ __forceinline__ uint32_t pk2(float lo, float hi){
    uint32_t r; asm("cvt.rn.bf16x2.f32 %0, %1, %2;" : "=r"(r) : "f"(hi), "f"(lo)); return r;
}
/* fast activations: 4 MUFU per hval */
__device__ __forceinline__ float tanhap(float x){
    float y; asm("tanh.approx.f32 %0, %1;" : "=f"(y) : "f"(x)); return y;
}
__device__ __forceinline__ float sigap(float x){ return fmaf(tanhap(0.5f*x), 0.5f, 0.5f); }
__device__ __forceinline__ float hval(float iv, float gv, float ov){
    float cv = sigap(iv) * tanhap(gv);
    return sigap(ov) * tanhap(cv);
}

/* ---- prep: weights -> pre-swizzled 12KB stages in consumption order ---- */
__global__ void pack_kernel(const float* __restrict__ W1,const float* __restrict__ b1i,const float* __restrict__ b1h,
                            const float* __restrict__ W2,const float* __restrict__ b2i,const float* __restrict__ b2h,
                            const float* __restrict__ W3,const float* __restrict__ b3i,const float* __restrict__ b3h){
    int idx = blockIdx.x*256 + threadIdx.x;
    if (idx < NSTAGES*6144){
        int ss = idx / 6144, e = idx % 6144;
        int nrow = e >> 6, kk = e & 63;
        int l, jc, kc;
        if (ss < 16){ l = 0; jc = ss >> 1; kc = ss & 1; }
        else if (ss < 48){ int s = ss-16; l = 1; jc = s >> 2; kc = s & 3; }
        else { int s = ss-48; l = 2; jc = s >> 2; kc = s & 3; }
        int g = nrow >> 5, n = nrow & 31;
        int H = (l<2) ? 256 : 128;
        int K = (l==0) ? 128 : 256;
        int j = jc*32 + n;
        int row = (g==0) ? j : (g==1) ? 2*H+j : 3*H+j;   /* gates i,g,o from i,f,g,o */
        const float* W = (l==0) ? W1 : (l==1) ? W2 : W3;
        float v = W[(size_t)row*K + kc*64 + kk];
        uint32_t off = (uint32_t)nrow*128u + ((((uint32_t)(kk>>3)) ^ (nrow&7))<<4) + ((2u*kk)&15);
        *reinterpret_cast<__nv_bfloat16*>(g_Wimg + (size_t)ss*12288 + off) = __float2bfloat16_rn(v);
        return;
    }
    idx -= NSTAGES*6144;
    if (idx < 1920){
        int l = (idx<768)?0:(idx<1536)?1:2;
        int base = (l==0)?0:(l==1)?768:1536;
        int H = (l<2)?256:128;
        int q = idx - base, g = q / H, j = q % H;
        int row = (g==0)? j : (g==1)? 2*H+j : 3*H+j;
        const float* bi = (l==0)?b1i:(l==1)?b2i:b3i;
        const float* bh = (l==0)?b1h:(l==1)?b2h:b3h;
        g_bias[idx] = bi[row] + bh[row];
    }
}

/* ---- prep: x (B,128,21) -> per-tile swizzled bf16 A images (row 256B) ---- */
__global__ void transpose_kernel(const float* __restrict__ x){
    __shared__ float sx[2688];
    int b = blockIdx.x, tid = threadIdx.x;   /* 256 threads */
    const float* xb = x + (size_t)b*2688;
    for (int i = tid; i < 2688; i += 256) sx[i] = xb[i];
    __syncthreads();
    for (int i = tid; i < 1344; i += 256){
        int t = i >> 6, kp = (i & 63) * 2;
        int m = b*21 + t, tt = m >> 7, r = m & 127;
        uint32_t v = pk2(sx[kp*21 + t], sx[(kp+1)*21 + t]);
        uint32_t off = (uint32_t)r*256u + ((((uint32_t)(kp>>3)) ^ (r&7))<<4) + ((2u*kp)&15);
        *reinterpret_cast<uint32_t*>(g_xA + (size_t)tt*32768 + off) = v;
    }
}

/* ---- weight stage fill: pure linear copy (image pre-swizzled) ---- */
__device__ __forceinline__ void fill_stage(char* smem, int s, int tid){
    char* dst = smem + SO_W + (uint32_t)(s&3)*12288u;
    const unsigned char* src = g_Wimg + (size_t)s*12288;
    #pragma unroll
    for (int it = 0; it < 3; ++it){
        int ch = tid + it*256;
        cpa16(dst + ch*16, src + ch*16);
    }
}

/* ---- epilogue for one h-pair q (0..7) of column-chunk pjc ---- */
template<int H, int LAST>
__device__ __forceinline__ void epi_pair(float (&accP)[3][2][2][4], int q, int pjc,
                                         char* Aout, const float* fcw, float* yp,
                                         int lane, int mw, int nw){
    const int nf = q >> 2, mf = (q >> 1) & 1, hf = q & 1;
    const int j0 = pjc*32 + nw*16 + nf*8 + 2*(lane & 3);
    const float h0 = hval(accP[0][mf][nf][2*hf],   accP[1][mf][nf][2*hf],   accP[2][mf][nf][2*hf]);
    const float h1 = hval(accP[0][mf][nf][2*hf+1], accP[1][mf][nf][2*hf+1], accP[2][mf][nf][2*hf+1]);
    if (!LAST){
        const uint32_t row = 32*mw + 16*mf + 8*hf + (lane>>2);
        const uint32_t b = 2u*(uint32_t)j0;
        const uint32_t off = row*(2u*H) + ((((b>>4) ^ (row&7)))<<4) + (b&15);
        *reinterpret_cast<uint32_t*>(Aout + off) = pk2(h0, h1);
    } else {
        yp[mf*2+hf] = fmaf(h0, fcw[j0], fmaf(h1, fcw[j0+1], yp[mf*2+hf]));
    }
}

/* ---- one jc pass: accumulate column-chunk jc into acc; if DEF, drain accP (jc=pjc) ---- */
template<int K, int H, int LAST, int DEF>
__device__ __forceinline__ void kc_pass(char* smem, const char* Ain, char* Aout,
                                        float (&acc)[3][2][2][4], float (&accP)[3][2][2][4],
                                        int jc, int pjc, int& ss,
                                        const float* biasL, const float* fcw, float* yp, int tid){
    const int wid = tid >> 5, lane = tid & 31;
    const int mw = wid >> 1, nw = wid & 1;
    const uint32_t arow = 32*mw + (lane & 15);
    const uint32_t ax = arow & 7;
    const uint32_t nrow = nw*16 + 8*(lane>>4) + (lane & 7);
    const uint32_t bx = nrow & 7;
    constexpr int NK = K/64;
    constexpr int CH = 8/NK;       /* h-pairs drained per kc */

    /* bias-folded accumulator init */
    {
        const int j0b = jc*32 + nw*16 + 2*(lane & 3);
        #pragma unroll
        for (int g = 0; g < 3; ++g){
            #pragma unroll
            for (int nf = 0; nf < 2; ++nf){
                const float b0v = biasL[g*H + j0b + nf*8];
                const float b1v = biasL[g*H + j0b + nf*8 + 1];
                #pragma unroll
                for (int mf = 0; mf < 2; ++mf){
                    #pragma unroll
                    for (int hf = 0; hf < 2; ++hf){
                        acc[g][mf][nf][2*hf]   = b0v;
                        acc[g][mf][nf][2*hf+1] = b1v;
                    }
                }
            }
        }
    }

    #pragma unroll
    for (int kc = 0; kc < NK; ++kc){
        cp_wait<2>();
        __syncthreads();               /* stage ss visible to all */
        const char* ws = smem + SO_W + (uint32_t)(ss&3)*12288u;
        #pragma unroll
        for (int ks = 0; ks < 4; ++ks){
            const uint32_t cA = (uint32_t)(kc*8 + 2*ks) + (lane>>4);
            const uint32_t aoff = arow*(2u*K) + (((cA ^ ax))<<4);
            uint32_t a0[4], a1[4];
            ldsm4(a0, Ain + aoff);
            ldsm4(a1, Ain + aoff + 32u*K);
            const uint32_t cb = (uint32_t)(2*ks) + ((lane>>3)&1);
            const uint32_t boff = nrow*128u + (((cb ^ bx))<<4);
            uint32_t b0[4], b1[4], b2[4];
            ldsm4(b0, ws + boff);
            ldsm4(b1, ws + boff + 4096);
            ldsm4(b2, ws + boff + 8192);
            mma16816(acc[0][0][0], a0, b0[0], b0[1]);
            mma16816(acc[0][0][1], a0, b0[2], b0[3]);
            mma16816(acc[0][1][0], a1, b0[0], b0[1]);
            mma16816(acc[0][1][1], a1, b0[2], b0[3]);
            mma16816(acc[1][0][0], a0, b1[0], b1[1]);
            mma16816(acc[1][0][1], a0, b1[2], b1[3]);
            mma16816(acc[1][1][0], a1, b1[0], b1[1]);
            mma16816(acc[1][1][1], a1, b1[2], b1[3]);
            mma16816(acc[2][0][0], a0, b2[0], b2[1]);
            mma16816(acc[2][0][1], a0, b2[2], b2[3]);
            mma16816(acc[2][1][0], a1, b2[0], b2[1]);
            mma16816(acc[2][1][1], a1, b2[2], b2[3]);
        }
        if (ss + 3 < NSTAGES) fill_stage(smem, ss + 3, tid);
        cp_commit();                   /* exactly one commit per kc */
        ++ss;
        if (DEF){                      /* drain previous jc in the tensor shadow */
            #pragma unroll
            for (int u = 0; u < CH; ++u)
                epi_pair<H,LAST>(accP, kc*CH + u, pjc, Aout, fcw, yp, lane, mw, nw);
        }
    }
}

/* ---- one fused layer with cross-jc software pipelining ---- */
template<int K, int H, int LAST>
__device__ __forceinline__ void run_layer(char* smem, const char* Ain, char* Aout,
                                          int& ss, const float* biasL, const float* fcw,
                                          float* yp, int tid){
    constexpr int NJ = H/32;           /* even: 8 or 4 */
    const int wid = tid >> 5, lane = tid & 31;
    const int mw = wid >> 1, nw = wid & 1;
    float accA[3][2][2][4], accB[3][2][2][4];

    kc_pass<K,H,LAST,0>(smem, Ain, Aout, accA, accB, 0, 0, ss, biasL, fcw, yp, tid);
    #pragma unroll 1
    for (int jcp = 0; jcp + 1 < NJ; jcp += 2){
        kc_pass<K,H,LAST,1>(smem, Ain, Aout, accB, accA, jcp+1, jcp,   ss, biasL, fcw, yp, tid);
        if (jcp + 2 < NJ)
            kc_pass<K,H,LAST,1>(smem, Ain, Aout, accA, accB, jcp+2, jcp+1, ss, biasL, fcw, yp, tid);
    }
    /* final serial drain: jc = NJ-1 lives in accB (NJ even) */
    #pragma unroll
    for (int q = 0; q < 8; ++q)
        epi_pair<H,LAST>(accB, q, NJ-1, Aout, fcw, yp, lane, mw, nw);
}

/* ---- fused main kernel: 3 LSTM layers + fc1 ---- */
__global__ void __launch_bounds__(256,1)
lstm_main(const float* __restrict__ fc1w, const float* __restrict__ fc1b){
    extern __shared__ char smem[];
    char* A0 = smem + SO_A0;
    char* A1 = smem + SO_A1;
    float* biasS = (float*)(smem + SO_BIAS);
    float* fcw   = (float*)(smem + SO_FCW);
    float* red   = (float*)(smem + SO_RED);
    const int tid = threadIdx.x, lane = tid & 31, wid = tid >> 5;
    const int mw = wid >> 1, nw = wid & 1;
    const float fc1b0 = __ldg(fc1b);

    /* x tile -> A0 */
    #pragma unroll
    for (int it = 0; it < 8; ++it){
        int ch = tid + it*256;
        cpa16(A0 + ch*16, g_xA + (size_t)blockIdx.x*32768 + ch*16);
    }
    cp_commit();
    fill_stage(smem, 0, tid); cp_commit();
    fill_stage(smem, 1, tid); cp_commit();
    fill_stage(smem, 2, tid); cp_commit();

    for (int i = tid; i < 1920; i += 256) biasS[i] = g_bias[i];
    if (tid < 128) fcw[tid] = fc1w[tid];

    int ss = 0;
    float yp[4] = {0.f, 0.f, 0.f, 0.f};
    run_layer<128,256,0>(smem, A0, A1, ss, biasS,        fcw, yp, tid);
    run_layer<256,256,0>(smem, A1, A0, ss, biasS + 768,  fcw, yp, tid);
    run_layer<256,128,1>(smem, A0, A1, ss, biasS + 1536, fcw, yp, tid);

    /* fc1 reduce: sum across quad lanes, then across nw halves */
    #pragma unroll
    for (int k = 0; k < 4; ++k){
        yp[k] += __shfl_xor_sync(0xffffffffu, yp[k], 1);
        yp[k] += __shfl_xor_sync(0xffffffffu, yp[k], 2);
    }
    __syncthreads();
    if (nw == 0 && (lane & 3) == 0){
        #pragma unroll
        for (int k = 0; k < 4; ++k){
            int row = 32*mw + 16*(k>>1) + 8*(k&1) + (lane>>2);
            red[row] = yp[k];
        }
    }
    __syncthreads();
    if (nw == 1 && (lane & 3) == 0){
        #pragma unroll
        for (int k = 0; k < 4; ++k){
            int row = 32*mw + 16*(k>>1) + 8*(k&1) + (lane>>2);
            g_y[(size_t)blockIdx.x*128 + row] = red[row] + yp[k] + fc1b0;
        }
    }
}

/* ---- fc2: out[b,0,t] = sum_j y[b,j]*w[t,j] + bias[t] ---- */
__global__ void fc2_kernel(const float* __restrict__ w, const float* __restrict__ bias,
                           float* __restrict__ out){
    __shared__ float sw[T_*T_];
    __shared__ float sbv[T_];
    int tid = threadIdx.x;
    for (int i = tid; i < T_*T_; i += 256) sw[i] = w[i];
    if (tid < T_) sbv[tid] = bias[tid];
    __syncthreads();
    int gidx = blockIdx.x*256 + tid;
    int b = gidx / T_, t = gidx - b*T_;
    const float* yb = g_y + (size_t)b*T_;
    float s = sbv[t];
    #pragma unroll
    for (int j = 0; j < T_; ++j) s += yb[j]*sw[t*T_ + j];
    out[gidx] = s;
}

/* ---- launch ---- */
extern "C" void kernel_launch(void* const* d_in, const int* in_sizes, int n_in,
                              void* d_out, int out_size){
    const float* x   = (const float*)d_in[0];
    const float* W1  = (const float*)d_in[1];
    const float* b1i = (const float*)d_in[2];
    const float* b1h = (const float*)d_in[3];
    const float* W2  = (const float*)d_in[4];
    const float* b2i = (const float*)d_in[5];
    const float* b2h = (const float*)d_in[6];
    const float* W3  = (const float*)d_in[7];
    const float* b3i = (const float*)d_in[8];
    const float* b3h = (const float*)d_in[9];
    const float* f1w = (const float*)d_in[10];
    const float* f1b = (const float*)d_in[11];
    const float* f2w = (const float*)d_in[12];
    const float* f2b = (const float*)d_in[13];
    float* out = (float*)d_out;

    cudaFuncSetAttribute(lstm_main, cudaFuncAttributeMaxDynamicSharedMemorySize, SMEM_TOT);

    pack_kernel<<<1544, 256>>>(W1,b1i,b1h,W2,b2i,b2h,W3,b3i,b3h);
    transpose_kernel<<<B_, 256>>>(x);
    lstm_main<<<NTILE, 256, SMEM_TOT>>>(f1w, f1b);
    fc2_kernel<<<M_/256, 256>>>(f2w, f2b, out);
}